// round 6
// baseline (speedup 1.0000x reference)
#include <cuda_runtime.h>
#include <cuda_fp16.h>
#include <cstdint>

// Problem dims (fixed by the reference)
#define QN   512
#define CN   512
#define TNT  128
#define DIN  512
#define DHD  256
#define KCORR (TNT * DHD)   // 32768
#define MAXLAG 4
#define NLAG  9             // lags -4..4
#define MROWS (QN * TNT)    // 65536

// ---------------------------------------------------------------------------
// Scratch (static device globals; no allocation allowed)
// ---------------------------------------------------------------------------
__device__ __half   g_Hh[MROWS * DHD];   // hidden hi (reused audio/video)
__device__ __half   g_Hl[MROWS * DHD];   // hidden lo
__device__ __half   g_Ahf[MROWS * DHD];  // audio hi fp16
__device__ uint8_t  g_A8 [MROWS * DHD];  // audio e4m3(x)
__device__ uint8_t  g_Al8[MROWS * DHD];  // audio e4m3(2048*lo)
__device__ __half   g_Phf[MROWS * DHD];  // video hi fp16
__device__ uint8_t  g_P8 [MROWS * DHD];  // video e4m3(x)
__device__ uint8_t  g_Pl8[MROWS * DHD];  // video e4m3(2048*lo)
__device__ float g_Wc[DHD * DHD];        // folded v_w2 @ W (fp32)
__device__ float g_bc[DHD];              // folded v_b2 @ W
// pre-split, pre-transposed weights: [N][K], K contiguous (fp16 hi/lo)
__device__ __half g_W1ah[DHD * DIN], g_W1al[DHD * DIN];
__device__ __half g_W1vh[DHD * DIN], g_W1vl[DHD * DIN];
__device__ __half g_W2ah[DHD * DHD], g_W2al[DHD * DHD];
__device__ __half g_Wcth[DHD * DHD], g_Wctl[DHD * DHD];
__device__ float g_S [NLAG * QN * CN];   // per-lag scores

// ---------------------------------------------------------------------------
// Portable PTX helpers (valid on compute_103 virtual target)
// ---------------------------------------------------------------------------
__device__ __forceinline__ uint32_t smem_u32(const void* p) {
    uint32_t a;
    asm("{ .reg .u64 t; cvta.to.shared.u64 t, %1; cvt.u32.u64 %0, t; }"
        : "=r"(a) : "l"(p));
    return a;
}

#define CP_ASYNC_16(dst, src) \
    asm volatile("cp.async.ca.shared.global [%0], [%1], 16;" \
        :: "r"(dst), "l"(src) : "memory")
#define CP_ASYNC_CG_16(dst, src) \
    asm volatile("cp.async.cg.shared.global [%0], [%1], 16;" \
        :: "r"(dst), "l"(src) : "memory")
#define CP_ASYNC_COMMIT() asm volatile("cp.async.commit_group;" ::: "memory")
#define CP_ASYNC_WAIT_1() asm volatile("cp.async.wait_group 1;" ::: "memory")
#define CP_ASYNC_WAIT_0() asm volatile("cp.async.wait_group 0;" ::: "memory")

#define LDSM_X4(r, addr) \
    asm volatile("ldmatrix.sync.aligned.m8n8.x4.shared.b16 {%0,%1,%2,%3}, [%4];" \
        : "=r"((r)[0]), "=r"((r)[1]), "=r"((r)[2]), "=r"((r)[3]) : "r"(addr))

#define LDS32(r, addr) \
    asm volatile("ld.shared.b32 %0, [%1];" : "=r"(r) : "r"(addr))

__device__ __forceinline__ void mma_f16(float* c, const uint32_t* a,
                                        const uint32_t* b) {
    asm volatile(
        "mma.sync.aligned.m16n8k16.row.col.f32.f16.f16.f32 "
        "{%0,%1,%2,%3}, {%4,%5,%6,%7}, {%8,%9}, {%0,%1,%2,%3};"
        : "+f"(c[0]), "+f"(c[1]), "+f"(c[2]), "+f"(c[3])
        : "r"(a[0]), "r"(a[1]), "r"(a[2]), "r"(a[3]), "r"(b[0]), "r"(b[1]));
}

__device__ __forceinline__ void mma_e4m3(float* c, const uint32_t* a,
                                         const uint32_t* b) {
    asm volatile(
        "mma.sync.aligned.m16n8k32.row.col.f32.e4m3.e4m3.f32 "
        "{%0,%1,%2,%3}, {%4,%5,%6,%7}, {%8,%9}, {%0,%1,%2,%3};"
        : "+f"(c[0]), "+f"(c[1]), "+f"(c[2]), "+f"(c[3])
        : "r"(a[0]), "r"(a[1]), "r"(a[2]), "r"(a[3]), "r"(b[0]), "r"(b[1]));
}

// pack two floats -> e4m3x2 (first operand to HIGH byte)
__device__ __forceinline__ uint16_t cvt_e4m3x2(float hi, float lo) {
    uint16_t u;
    asm("cvt.rn.satfinite.e4m3x2.f32 %0, %1, %2;" : "=h"(u) : "f"(hi), "f"(lo));
    return u;
}

// ---------------------------------------------------------------------------
// Prep: fold v_w2 @ W -> g_Wc, g_bc
// ---------------------------------------------------------------------------
__global__ void prep_w_kernel(const float* __restrict__ v_w2,
                              const float* __restrict__ v_b2,
                              const float* __restrict__ W) {
    int i = blockIdx.x;
    int j = threadIdx.x;
    float acc = 0.f;
    #pragma unroll 8
    for (int k = 0; k < DHD; ++k)
        acc += v_w2[i * DHD + k] * W[k * DHD + j];
    g_Wc[i * DHD + j] = acc;
    if (i == 0) {
        float accb = 0.f;
        #pragma unroll 8
        for (int k = 0; k < DHD; ++k)
            accb += v_b2[k] * W[k * DHD + j];
        g_bc[j] = accb;
    }
}

// Prep: transpose + split fp32 [K, 256] -> fp16 hi/lo [256][K]
__global__ void split_t_kernel(const float* __restrict__ in,
                               __half* __restrict__ oh,
                               __half* __restrict__ ol, int K) {
    int n = blockIdx.x;
    for (int k = threadIdx.x; k < K; k += blockDim.x) {
        float v = in[(size_t)k * DHD + n];
        __half h = __float2half_rn(v);
        __half l = __float2half_rn(v - __half2float(h));
        oh[(size_t)n * K + k] = h;
        ol[(size_t)n * K + k] = l;
    }
}

// ---------------------------------------------------------------------------
// MLP tiling constants
// ---------------------------------------------------------------------------
#define BKC     32                  // K elems per chunk (MLP)
#define ROWB    80                  // padded row stride bytes (64 data + 16)
#define TILE_PB (128 * ROWB)        // 10240
#define BUF_PB  (4 * TILE_PB)       // 4 tiles: Ah, Al, Bh, Bl
#define HMMA_SMEM (2 * BUF_PB)      // 81920

extern __shared__ char dsm[];

// ---------------------------------------------------------------------------
// MLP GEMM on HMMA (fp16 3-term split)
//   layer1 (CONVERT_A=1, FP8OUT=0): fp32 in -> split -> fp16 hi/lo out
//   layer2 (CONVERT_A=0, FP8OUT=1): fp16 hi/lo in -> fp16 hi + fp8 pair out
// ---------------------------------------------------------------------------
template <bool CONVERT_A, bool RELU, bool FP8OUT>
__global__ __launch_bounds__(256, 1)
void mlp_hmma_kernel(const float* __restrict__ Af,
                     const __half* __restrict__ Ahg,
                     const __half* __restrict__ Alg,
                     const __half* __restrict__ Bh,
                     const __half* __restrict__ Bl,
                     const float* __restrict__ bias,
                     __half* __restrict__ Oh,
                     __half* __restrict__ Ol,
                     uint8_t* __restrict__ O8,
                     uint8_t* __restrict__ Ol8,
                     int K) {
    const uint32_t sb = smem_u32(dsm);
    const int tid  = threadIdx.x;
    const int wid  = tid >> 5;
    const int lane = tid & 31;
    const int bm = blockIdx.x * 128;
    const int bn = blockIdx.y * 128;
    const int NCH = K / BKC;

    const int wm = (wid >> 2) * 64;
    const int wn = (wid & 3) * 32;

    float acc[4][4][4];
    #pragma unroll
    for (int mi = 0; mi < 4; ++mi)
        #pragma unroll
        for (int nf = 0; nf < 4; ++nf)
            #pragma unroll
            for (int r = 0; r < 4; ++r) acc[mi][nf][r] = 0.f;

    const int aRow = wm + (lane & 15);
    const int aSeg = (lane >> 4) << 4;
    const int bg   = lane >> 3;
    const int bRow = wn + ((bg >> 1) << 3) + (lane & 7);
    const int bSeg = (bg & 1) << 4;

    float4 areg[4];

    auto prefetch_B = [&](int c, int buf) {
        const int k0 = c * BKC;
        const uint32_t base = sb + buf * BUF_PB;
        #pragma unroll
        for (int i = 0; i < 4; ++i) {
            int u = tid + i * 256;
            int tile = 2 + (u >> 9);
            int w = u & 511;
            int row = w >> 2, seg = w & 3;
            uint32_t dst = base + tile * TILE_PB + row * ROWB + seg * 16;
            const __half* src =
                ((u >> 9) == 0 ? Bh : Bl) + (size_t)(bn + row) * K + k0 + seg * 8;
            CP_ASYNC_16(dst, src);
        }
    };
    auto prefetch_A_f16 = [&](int c, int buf) {
        const int k0 = c * BKC;
        const uint32_t base = sb + buf * BUF_PB;
        #pragma unroll
        for (int i = 0; i < 4; ++i) {
            int u = tid + i * 256;
            int tile = u >> 9;
            int w = u & 511;
            int row = w >> 2, seg = w & 3;
            uint32_t dst = base + tile * TILE_PB + row * ROWB + seg * 16;
            const __half* src =
                (tile == 0 ? Ahg : Alg) + (size_t)(bm + row) * K + k0 + seg * 8;
            CP_ASYNC_16(dst, src);
        }
    };
    auto ldg_A_f32 = [&](int c) {
        const int k0 = c * BKC;
        #pragma unroll
        for (int i = 0; i < 4; ++i) {
            int s = tid + i * 256;
            int row = s >> 3, seg = s & 7;
            areg[i] = *(const float4*)&Af[(size_t)(bm + row) * K + k0 + seg * 4];
        }
    };
    auto sts_A_split = [&](int buf) {
        const uint32_t base = sb + buf * BUF_PB;
        #pragma unroll
        for (int i = 0; i < 4; ++i) {
            int s = tid + i * 256;
            int row = s >> 3, seg = s & 7;
            uint32_t off = row * ROWB + seg * 8;
            float4 v = areg[i];
            __half hx = __float2half_rn(v.x);
            __half hy = __float2half_rn(v.y);
            __half hz = __float2half_rn(v.z);
            __half hw = __float2half_rn(v.w);
            __half2 h01 = __halves2half2(hx, hy);
            __half2 h23 = __halves2half2(hz, hw);
            __half2 l01 = __halves2half2(
                __float2half_rn(v.x - __half2float(hx)),
                __float2half_rn(v.y - __half2float(hy)));
            __half2 l23 = __halves2half2(
                __float2half_rn(v.z - __half2float(hz)),
                __float2half_rn(v.w - __half2float(hw)));
            uint32_t hu0 = *(uint32_t*)&h01, hu1 = *(uint32_t*)&h23;
            uint32_t lu0 = *(uint32_t*)&l01, lu1 = *(uint32_t*)&l23;
            asm volatile("st.shared.v2.b32 [%0], {%1, %2};"
                         :: "r"(base + 0 * TILE_PB + off), "r"(hu0), "r"(hu1) : "memory");
            asm volatile("st.shared.v2.b32 [%0], {%1, %2};"
                         :: "r"(base + 1 * TILE_PB + off), "r"(lu0), "r"(lu1) : "memory");
        }
    };

    if (CONVERT_A) {
        ldg_A_f32(0);
        prefetch_B(0, 0);
        CP_ASYNC_COMMIT();
    } else {
        prefetch_A_f16(0, 0);
        prefetch_B(0, 0);
        CP_ASYNC_COMMIT();
    }

    for (int c = 0; c < NCH; ++c) {
        const int buf = c & 1;
        if (CONVERT_A) {
            sts_A_split(buf);
            if (c + 1 < NCH) {
                prefetch_B(c + 1, buf ^ 1);
                CP_ASYNC_COMMIT();
                CP_ASYNC_WAIT_1();
            } else {
                CP_ASYNC_WAIT_0();
            }
            __syncthreads();
            if (c + 1 < NCH) ldg_A_f32(c + 1);
        } else {
            if (c + 1 < NCH) {
                prefetch_A_f16(c + 1, buf ^ 1);
                prefetch_B(c + 1, buf ^ 1);
                CP_ASYNC_COMMIT();
                CP_ASYNC_WAIT_1();
            } else {
                CP_ASYNC_WAIT_0();
            }
            __syncthreads();
        }

        const uint32_t tb  = sb + buf * BUF_PB;
        const uint32_t ahB = tb + 0 * TILE_PB;
        const uint32_t alB = tb + 1 * TILE_PB;
        const uint32_t bhB = tb + 2 * TILE_PB;
        const uint32_t blB = tb + 3 * TILE_PB;

        #pragma unroll
        for (int ks = 0; ks < 2; ++ks) {
            const int kbyte = ks * 32;
            uint32_t ah[4][4], al[4][4], ph[4][2], pl[4][2];
            #pragma unroll
            for (int mi = 0; mi < 4; ++mi) {
                uint32_t off = (uint32_t)(aRow + mi * 16) * ROWB + kbyte + aSeg;
                LDSM_X4(ah[mi], ahB + off);
                LDSM_X4(al[mi], alB + off);
            }
            #pragma unroll
            for (int ni = 0; ni < 2; ++ni) {
                uint32_t off = (uint32_t)(bRow + ni * 16) * ROWB + kbyte + bSeg;
                uint32_t r[4];
                LDSM_X4(r, bhB + off);
                ph[2 * ni][0] = r[0]; ph[2 * ni][1] = r[1];
                ph[2 * ni + 1][0] = r[2]; ph[2 * ni + 1][1] = r[3];
                LDSM_X4(r, blB + off);
                pl[2 * ni][0] = r[0]; pl[2 * ni][1] = r[1];
                pl[2 * ni + 1][0] = r[2]; pl[2 * ni + 1][1] = r[3];
            }
            #pragma unroll
            for (int mi = 0; mi < 4; ++mi)
                #pragma unroll
                for (int nf = 0; nf < 4; ++nf) {
                    mma_f16(acc[mi][nf], ah[mi], ph[nf]);
                    mma_f16(acc[mi][nf], ah[mi], pl[nf]);
                    mma_f16(acc[mi][nf], al[mi], ph[nf]);
                }
        }
        __syncthreads();
    }

    #pragma unroll
    for (int mi = 0; mi < 4; ++mi) {
        int r0 = bm + wm + mi * 16 + (lane >> 2);
        #pragma unroll
        for (int nf = 0; nf < 4; ++nf) {
            int cn = bn + wn + nf * 8 + 2 * (lane & 3);
            float b0 = bias[cn], b1 = bias[cn + 1];
            #pragma unroll
            for (int half_ = 0; half_ < 2; ++half_) {
                int r = r0 + half_ * 8;
                float o0 = acc[mi][nf][2 * half_ + 0] + b0;
                float o1 = acc[mi][nf][2 * half_ + 1] + b1;
                if (RELU) { o0 = fmaxf(o0, 0.f); o1 = fmaxf(o1, 0.f); }
                __half h0 = __float2half_rn(o0);
                __half h1 = __float2half_rn(o1);
                __half2 hh = __halves2half2(h0, h1);
                float l0 = o0 - __half2float(h0);
                float l1 = o1 - __half2float(h1);
                *(__half2*)&Oh[(size_t)r * DHD + cn] = hh;
                if (FP8OUT) {
                    *(uint16_t*)&O8 [(size_t)r * DHD + cn] = cvt_e4m3x2(o1, o0);
                    *(uint16_t*)&Ol8[(size_t)r * DHD + cn] =
                        cvt_e4m3x2(2048.f * l1, 2048.f * l0);
                } else {
                    __half2 ll = __halves2half2(__float2half_rn(l0),
                                                __float2half_rn(l1));
                    *(__half2*)&Ol[(size_t)r * DHD + cn] = ll;
                }
            }
        }
    }
}

// ---------------------------------------------------------------------------
// Correlation, hybrid precision:
//   S = Ah*Ph (fp16 m16n8k16) + (1/2048)*(A8*Pl8 + Al8*P8) (e4m3 m16n8k32)
// one CTA per (q-tile 128, c-tile 128, lag); 8 warps, warp tile 64x32.
// K chunks of 64; double-buffered cp.async staging.
// ---------------------------------------------------------------------------
#define BKC2     64
#define NCHUNK2  (KCORR / BKC2)      // 512
#define ROWH     144                 // fp16 tile: 128B data + 16 pad
#define TILEH    (128 * ROWH)        // 18432
#define ROW8     80                  // fp8 tile: 64B data + 16 pad
#define TILE8    (128 * ROW8)        // 10240
#define OFF_AH   0
#define OFF_PH   (OFF_AH + TILEH)            // 18432
#define OFF_A8   (OFF_PH + TILEH)            // 36864
#define OFF_AL8  (OFF_A8 + TILE8)            // 47104
#define OFF_P8   (OFF_AL8 + TILE8)           // 57344
#define OFF_PL8  (OFF_P8 + TILE8)            // 67584
#define BUF3_PB  (OFF_PL8 + TILE8)           // 77824
#define CORR_SMEM (2 * BUF3_PB)              // 155648

__device__ __forceinline__ void corr_prefetch3(
    uint32_t sb, int buf, int c, int bm, int bn, int lag,
    const __half* __restrict__ Ah, const __half* __restrict__ Ph,
    const uint8_t* __restrict__ A8, const uint8_t* __restrict__ Al8,
    const uint8_t* __restrict__ P8, const uint8_t* __restrict__ Pl8,
    int tid)
{
    const int k0 = c * BKC2;
    const int t  = c >> 2;                       // k0 / 256
    const int d0 = (c & 3) << 6;                 // k0 % 256
    const int ts = (t + lag + TNT) & (TNT - 1);
    const int kb = ts * DHD + d0;

    const uint32_t base = sb + buf * BUF3_PB;
    #pragma unroll
    for (int i = 0; i < 16; ++i) {
        int u = tid + i * 256;                   // 0..4095
        uint32_t dst;
        const void* src;
        if (u < 1024) {                          // Ah fp16
            int row = u >> 3, seg = u & 7;
            dst = base + OFF_AH + row * ROWH + seg * 16;
            src = Ah + (size_t)(bm + row) * KCORR + k0 + seg * 8;
        } else if (u < 2048) {                   // Ph fp16 (shifted)
            int w = u - 1024;
            int row = w >> 3, seg = w & 7;
            dst = base + OFF_PH + row * ROWH + seg * 16;
            src = Ph + (size_t)(bn + row) * KCORR + kb + seg * 8;
        } else if (u < 2560) {                   // A8
            int w = u - 2048;
            int row = w >> 2, seg = w & 3;
            dst = base + OFF_A8 + row * ROW8 + seg * 16;
            src = A8 + (size_t)(bm + row) * KCORR + k0 + seg * 16;
        } else if (u < 3072) {                   // Al8
            int w = u - 2560;
            int row = w >> 2, seg = w & 3;
            dst = base + OFF_AL8 + row * ROW8 + seg * 16;
            src = Al8 + (size_t)(bm + row) * KCORR + k0 + seg * 16;
        } else if (u < 3584) {                   // P8 (shifted)
            int w = u - 3072;
            int row = w >> 2, seg = w & 3;
            dst = base + OFF_P8 + row * ROW8 + seg * 16;
            src = P8 + (size_t)(bn + row) * KCORR + kb + seg * 16;
        } else {                                 // Pl8 (shifted)
            int w = u - 3584;
            int row = w >> 2, seg = w & 3;
            dst = base + OFF_PL8 + row * ROW8 + seg * 16;
            src = Pl8 + (size_t)(bn + row) * KCORR + kb + seg * 16;
        }
        CP_ASYNC_CG_16(dst, src);
    }
    CP_ASYNC_COMMIT();
}

__global__ __launch_bounds__(256, 1)
void corr_hmma_kernel(const __half* __restrict__ Ah,
                      const __half* __restrict__ Ph,
                      const uint8_t* __restrict__ A8,
                      const uint8_t* __restrict__ Al8,
                      const uint8_t* __restrict__ P8,
                      const uint8_t* __restrict__ Pl8) {
    const uint32_t sb = smem_u32(dsm);
    const int tid  = threadIdx.x;
    const int wid  = tid >> 5;
    const int lane = tid & 31;
    const int bm = blockIdx.x * 128;
    const int bn = blockIdx.y * 128;
    const int lag = (int)blockIdx.z - MAXLAG;

    const int wm = (wid >> 2) * 64;
    const int wn = (wid & 3) * 32;

    float acc [4][4][4];   // hi*hi
    float accC[4][4][4];   // scaled cross terms
    #pragma unroll
    for (int mi = 0; mi < 4; ++mi)
        #pragma unroll
        for (int nf = 0; nf < 4; ++nf)
            #pragma unroll
            for (int r = 0; r < 4; ++r) { acc[mi][nf][r] = 0.f; accC[mi][nf][r] = 0.f; }

    // fp16 ldmatrix addressing
    const int aRow = wm + (lane & 15);
    const int aSeg = (lane >> 4) << 4;
    const int bg   = lane >> 3;
    const int bRow = wn + ((bg >> 1) << 3) + (lane & 7);
    const int bSeg = (bg & 1) << 4;

    // fp8 per-lane addressing
    const int q4 = (lane & 3) * 4;     // k byte offset within step
    const int r4 = lane >> 2;          // row-in-8

    corr_prefetch3(sb, 0, 0, bm, bn, lag, Ah, Ph, A8, Al8, P8, Pl8, tid);

    for (int c = 0; c < NCHUNK2; ++c) {
        const int buf = c & 1;
        if (c + 1 < NCHUNK2) {
            corr_prefetch3(sb, buf ^ 1, c + 1, bm, bn, lag,
                           Ah, Ph, A8, Al8, P8, Pl8, tid);
            CP_ASYNC_WAIT_1();
        } else {
            CP_ASYNC_WAIT_0();
        }
        __syncthreads();

        const uint32_t tb   = sb + buf * BUF3_PB;
        const uint32_t ahB  = tb + OFF_AH;
        const uint32_t phB  = tb + OFF_PH;
        const uint32_t a8B  = tb + OFF_A8;
        const uint32_t al8B = tb + OFF_AL8;
        const uint32_t p8B  = tb + OFF_P8;
        const uint32_t pl8B = tb + OFF_PL8;

        // ---- hi*hi fp16 term: 4 k16 steps ----
        #pragma unroll
        for (int ks = 0; ks < 4; ++ks) {
            const int kbyte = ks * 32;
            uint32_t ahf[4][4], phf[4][2];
            #pragma unroll
            for (int mi = 0; mi < 4; ++mi) {
                uint32_t off = (uint32_t)(aRow + mi * 16) * ROWH + kbyte + aSeg;
                LDSM_X4(ahf[mi], ahB + off);
            }
            #pragma unroll
            for (int ni = 0; ni < 2; ++ni) {
                uint32_t off = (uint32_t)(bRow + ni * 16) * ROWH + kbyte + bSeg;
                uint32_t r[4];
                LDSM_X4(r, phB + off);
                phf[2 * ni][0] = r[0]; phf[2 * ni][1] = r[1];
                phf[2 * ni + 1][0] = r[2]; phf[2 * ni + 1][1] = r[3];
            }
            #pragma unroll
            for (int mi = 0; mi < 4; ++mi)
                #pragma unroll
                for (int nf = 0; nf < 4; ++nf)
                    mma_f16(acc[mi][nf], ahf[mi], phf[nf]);
        }

        // ---- cross terms fp8: 2 k32 steps ----
        #pragma unroll
        for (int ks2 = 0; ks2 < 2; ++ks2) {
            const int kb8 = ks2 * 32 + q4;
            uint32_t a8f[4][4], al8f[4][4], b8f[4][2], bl8f[4][2];
            #pragma unroll
            for (int mi = 0; mi < 4; ++mi) {
                uint32_t base0 = (uint32_t)(wm + mi * 16 + r4) * ROW8 + kb8;
                uint32_t base1 = base0 + 8 * ROW8;
                LDS32(a8f[mi][0], a8B + base0);
                LDS32(a8f[mi][1], a8B + base1);
                LDS32(a8f[mi][2], a8B + base0 + 16);
                LDS32(a8f[mi][3], a8B + base1 + 16);
                LDS32(al8f[mi][0], al8B + base0);
                LDS32(al8f[mi][1], al8B + base1);
                LDS32(al8f[mi][2], al8B + base0 + 16);
                LDS32(al8f[mi][3], al8B + base1 + 16);
            }
            #pragma unroll
            for (int nf = 0; nf < 4; ++nf) {
                uint32_t base0 = (uint32_t)(wn + nf * 8 + r4) * ROW8 + kb8;
                LDS32(b8f[nf][0], p8B + base0);
                LDS32(b8f[nf][1], p8B + base0 + 16);
                LDS32(bl8f[nf][0], pl8B + base0);
                LDS32(bl8f[nf][1], pl8B + base0 + 16);
            }
            #pragma unroll
            for (int mi = 0; mi < 4; ++mi)
                #pragma unroll
                for (int nf = 0; nf < 4; ++nf) {
                    mma_e4m3(accC[mi][nf], a8f[mi], bl8f[nf]);   // x * (2048 lo_p)
                    mma_e4m3(accC[mi][nf], al8f[mi], b8f[nf]);   // (2048 lo_a) * x
                }
        }
        __syncthreads();
    }

    float* Sz = g_S + (size_t)blockIdx.z * QN * CN;
    const float cscale = 1.f / 2048.f;
    #pragma unroll
    for (int mi = 0; mi < 4; ++mi) {
        int r0 = bm + wm + mi * 16 + (lane >> 2);
        #pragma unroll
        for (int nf = 0; nf < 4; ++nf) {
            int col = bn + wn + nf * 8 + 2 * (lane & 3);
            float2 v0 = {acc[mi][nf][0] + cscale * accC[mi][nf][0],
                         acc[mi][nf][1] + cscale * accC[mi][nf][1]};
            float2 v1 = {acc[mi][nf][2] + cscale * accC[mi][nf][2],
                         acc[mi][nf][3] + cscale * accC[mi][nf][3]};
            *(float2*)&Sz[(size_t)r0 * CN + col]       = v0;
            *(float2*)&Sz[(size_t)(r0 + 8) * CN + col] = v1;
        }
    }
}

// ---------------------------------------------------------------------------
// Final max over lags
// ---------------------------------------------------------------------------
__global__ void maxlag_kernel(float* __restrict__ out) {
    int idx = blockIdx.x * blockDim.x + threadIdx.x;
    float m = g_S[idx];
    #pragma unroll
    for (int j = 1; j < NLAG; ++j)
        m = fmaxf(m, g_S[(size_t)j * QN * CN + idx]);
    out[idx] = m;
}

// ---------------------------------------------------------------------------
// Launch
// ---------------------------------------------------------------------------
extern "C" void kernel_launch(void* const* d_in, const int* in_sizes, int n_in,
                              void* d_out, int out_size) {
    const float* audio = (const float*)d_in[0];
    const float* video = (const float*)d_in[1];
    const float* a_w1  = (const float*)d_in[2];
    const float* a_b1  = (const float*)d_in[3];
    const float* a_w2  = (const float*)d_in[4];
    const float* a_b2  = (const float*)d_in[5];
    const float* v_w1  = (const float*)d_in[6];
    const float* v_b1  = (const float*)d_in[7];
    const float* v_w2  = (const float*)d_in[8];
    const float* v_b2  = (const float*)d_in[9];
    const float* W     = (const float*)d_in[10];
    float* out = (float*)d_out;

    float *gWc, *gbc;
    __half *gHh, *gHl, *gAhf, *gPhf;
    uint8_t *gA8, *gAl8, *gP8, *gPl8;
    __half *gW1ah, *gW1al, *gW1vh, *gW1vl, *gW2ah, *gW2al, *gWcth, *gWctl;
    cudaGetSymbolAddress((void**)&gHh, g_Hh);
    cudaGetSymbolAddress((void**)&gHl, g_Hl);
    cudaGetSymbolAddress((void**)&gAhf, g_Ahf);
    cudaGetSymbolAddress((void**)&gA8,  g_A8);
    cudaGetSymbolAddress((void**)&gAl8, g_Al8);
    cudaGetSymbolAddress((void**)&gPhf, g_Phf);
    cudaGetSymbolAddress((void**)&gP8,  g_P8);
    cudaGetSymbolAddress((void**)&gPl8, g_Pl8);
    cudaGetSymbolAddress((void**)&gWc, g_Wc);
    cudaGetSymbolAddress((void**)&gbc, g_bc);
    cudaGetSymbolAddress((void**)&gW1ah, g_W1ah);
    cudaGetSymbolAddress((void**)&gW1al, g_W1al);
    cudaGetSymbolAddress((void**)&gW1vh, g_W1vh);
    cudaGetSymbolAddress((void**)&gW1vl, g_W1vl);
    cudaGetSymbolAddress((void**)&gW2ah, g_W2ah);
    cudaGetSymbolAddress((void**)&gW2al, g_W2al);
    cudaGetSymbolAddress((void**)&gWcth, g_Wcth);
    cudaGetSymbolAddress((void**)&gWctl, g_Wctl);

    cudaFuncSetAttribute(corr_hmma_kernel,
                         cudaFuncAttributeMaxDynamicSharedMemorySize, CORR_SMEM);
    cudaFuncSetAttribute(mlp_hmma_kernel<true, true, false>,
                         cudaFuncAttributeMaxDynamicSharedMemorySize, HMMA_SMEM);
    cudaFuncSetAttribute(mlp_hmma_kernel<false, false, true>,
                         cudaFuncAttributeMaxDynamicSharedMemorySize, HMMA_SMEM);

    // 0) prep: fold Wc, split+transpose all weights
    prep_w_kernel<<<DHD, DHD>>>(v_w2, v_b2, W);
    split_t_kernel<<<DHD, 256>>>(a_w1, gW1ah, gW1al, DIN);
    split_t_kernel<<<DHD, 256>>>(v_w1, gW1vh, gW1vl, DIN);
    split_t_kernel<<<DHD, 256>>>(a_w2, gW2ah, gW2al, DHD);
    split_t_kernel<<<DHD, 256>>>(gWc,  gWcth, gWctl, DHD);

    const dim3 mlp_grid(MROWS / 128, DHD / 128);   // 512 x 2

    // 1) audio MLP on HMMA
    mlp_hmma_kernel<true,  true,  false><<<mlp_grid, 256, HMMA_SMEM>>>(
        audio, nullptr, nullptr, gW1ah, gW1al, a_b1,
        gHh, gHl, nullptr, nullptr, DIN);
    mlp_hmma_kernel<false, false, true ><<<mlp_grid, 256, HMMA_SMEM>>>(
        nullptr, gHh, gHl, gW2ah, gW2al, a_b2,
        gAhf, nullptr, gA8, gAl8, DHD);

    // 2) video MLP + folded projection on HMMA
    mlp_hmma_kernel<true,  true,  false><<<mlp_grid, 256, HMMA_SMEM>>>(
        video, nullptr, nullptr, gW1vh, gW1vl, v_b1,
        gHh, gHl, nullptr, nullptr, DIN);
    mlp_hmma_kernel<false, false, true ><<<mlp_grid, 256, HMMA_SMEM>>>(
        nullptr, gHh, gHl, gWcth, gWctl, gbc,
        gPhf, nullptr, gP8, gPl8, DHD);

    // 3) per-lag correlation, hybrid fp16/fp8 (144 CTAs, one wave)
    corr_hmma_kernel<<<dim3(QN / 128, CN / 128, NLAG), 256, CORR_SMEM>>>(
        gAhf, gPhf, gA8, gAl8, gP8, gPl8);

    // 4) max over lags
    maxlag_kernel<<<(QN * CN) / 256, 256>>>(out);
}